// round 4
// baseline (speedup 1.0000x reference)
#include <cuda_runtime.h>

#define NB   64
#define HIN  480
#define WIN  80
#define C0   8
#define C1   16
#define C2   16
#define C3   32
#define H2   160
#define W2   40
#define TT   40
#define W5   20
#define IG   640
#define HID  256
#define G3   768

// ---------------- device scratch ----------------
__device__ float g_tmp0[NB*C0*HIN*WIN];   // conv0 out (relu)
__device__ float g_tmp1[NB*C1*H2*W2];     // pool(relu(conv1))
__device__ float g_tmp2[NB*C2*H2*W2];     // relu(conv2)
__device__ float g_x[NB*TT*IG];           // GRU input (b,t,640)
__device__ float g_gx[2*TT*NB*G3];        // gate preacts, both dirs
__device__ float g_h[2][2*NB*HID];        // double-buffered hidden
__device__ unsigned g_ctr[16];            // per-group barrier counters

// packed fp32x2 FMA (Blackwell)
__device__ __forceinline__ float2 ffma2(float2 w, float x, float2 c) {
    float2 r;
    asm("{\n\t"
        ".reg .b64 wa, xb, cc, dd;\n\t"
        "mov.b64 wa, {%2,%3};\n\t"
        "mov.b64 xb, {%4,%4};\n\t"
        "mov.b64 cc, {%5,%6};\n\t"
        "fma.rn.f32x2 dd, wa, xb, cc;\n\t"
        "mov.b64 {%0,%1}, dd;\n\t"
        "}" : "=f"(r.x), "=f"(r.y)
            : "f"(w.x), "f"(w.y), "f"(x), "f"(c.x), "f"(c.y));
    return r;
}
__device__ __forceinline__ float2 fmax2(float2 a, float2 b) {
    return make_float2(fmaxf(a.x,b.x), fmaxf(a.y,b.y));
}

// ---------------- prep: h0 + barrier counters ----------------
__global__ void k_prep(const float* __restrict__ hidden) {
    int i = blockIdx.x*256 + threadIdx.x;
    if (i < 2*NB*HID) g_h[0][i] = hidden[i];
    if (i < 16) g_ctr[i] = 0u;
}

// ---------------- conv0: 1->8, 3x3 pad1, relu ----------------
__global__ __launch_bounds__(256) void k_conv0(const float* __restrict__ in,
                                               const float* __restrict__ w,
                                               const float* __restrict__ bias) {
    __shared__ float2 sw[36];
    __shared__ float2 sb[4];
    int tid = threadIdx.x;
    if (tid < 36) { int ocp = tid/9, k = tid%9;
        sw[tid] = make_float2(w[(2*ocp)*9+k], w[(2*ocp+1)*9+k]); }
    if (tid < 4) sb[tid] = make_float2(bias[2*tid], bias[2*tid+1]);
    __syncthreads();
    int gid = blockIdx.x*256 + tid;
    int x = gid % WIN; int y = (gid/WIN) % HIN; int b = gid/(WIN*HIN);
    const float* ip = in + (size_t)b*HIN*WIN;
    float v[9];
#pragma unroll
    for (int dy=0; dy<3; dy++)
#pragma unroll
    for (int dx=0; dx<3; dx++) {
        int yy = y+dy-1, xx = x+dx-1;
        v[dy*3+dx] = (yy>=0 && yy<HIN && xx>=0 && xx<WIN) ? ip[yy*WIN+xx] : 0.f;
    }
#pragma unroll
    for (int ocp=0; ocp<4; ocp++) {
        float2 acc = sb[ocp];
#pragma unroll
        for (int k=0;k<9;k++) acc = ffma2(sw[ocp*9+k], v[k], acc);
        g_tmp0[((b*C0 + 2*ocp  )*HIN + y)*WIN + x] = fmaxf(acc.x, 0.f);
        g_tmp0[((b*C0 + 2*ocp+1)*HIN + y)*WIN + x] = fmaxf(acc.y, 0.f);
    }
}

// ---------------- conv1 (8->16) + relu + maxpool(3,2) ----------------
__global__ __launch_bounds__(160) void k_conv1pool(const float* __restrict__ w,
                                                   const float* __restrict__ bias) {
    __shared__ float  s_in[8*14*82];
    __shared__ float2 s_w[8*72];
    __shared__ float2 s_b[8];
    int tid = threadIdx.x;
    int b = blockIdx.x/40, tile = blockIdx.x%40;
    for (int i=tid; i<576; i+=160) {
        int ocp = i/72, rem = i%72;
        s_w[i] = make_float2(w[(2*ocp)*72+rem], w[(2*ocp+1)*72+rem]);
    }
    if (tid<8) s_b[tid] = make_float2(bias[2*tid], bias[2*tid+1]);
    int row0g = tile*12 - 1;
    for (int i=tid; i<9184; i+=160) {
        int ic = i/1148; int rem = i%1148; int r = rem/82, c = rem%82;
        int ih = row0g + r, iw = c - 1;
        float v = 0.f;
        if (ih>=0 && ih<HIN && iw>=0 && iw<WIN)
            v = g_tmp0[((b*C0+ic)*HIN+ih)*WIN+iw];
        s_in[i] = v;
    }
    __syncthreads();
    int oh_l = tid/40, ow = tid%40;
    float2 acc[6][8];
#pragma unroll
    for (int p=0;p<6;p++)
#pragma unroll
    for (int o=0;o<8;o++) acc[p][o] = s_b[o];
#pragma unroll 1
    for (int ic=0; ic<8; ic++) {
        const float* sp = s_in + ic*1148;
#pragma unroll
        for (int k=0;k<9;k++) {
            int dy = k/3, dx = k%3;
            float2 wv[8];
#pragma unroll
            for (int o=0;o<8;o++) wv[o] = s_w[o*72 + ic*9 + k];
#pragma unroll
            for (int pr=0;pr<3;pr++)
#pragma unroll
            for (int pc=0;pc<2;pc++) {
                float xv = sp[(oh_l*3+pr+dy)*82 + (2*ow+pc+dx)];
                int p = pr*2+pc;
#pragma unroll
                for (int o=0;o<8;o++) acc[p][o] = ffma2(wv[o], xv, acc[p][o]);
            }
        }
    }
    int oh = tile*4 + oh_l;
#pragma unroll
    for (int o=0;o<8;o++) {
        float2 m = acc[0][o];
#pragma unroll
        for (int p=1;p<6;p++) m = fmax2(m, acc[p][o]);
        g_tmp1[((b*C1 + 2*o  )*H2 + oh)*W2 + ow] = fmaxf(m.x, 0.f);
        g_tmp1[((b*C1 + 2*o+1)*H2 + oh)*W2 + ow] = fmaxf(m.y, 0.f);
    }
}

// ---------------- conv2: 16->16, 3x3 pad1, relu ----------------
__global__ __launch_bounds__(160) void k_conv2(const float* __restrict__ w,
                                               const float* __restrict__ bias) {
    __shared__ float  s_in[16*10*42];
    __shared__ float2 s_w[8*144];
    __shared__ float2 s_b[8];
    int tid = threadIdx.x;
    int b = blockIdx.x/20, tile = blockIdx.x%20;
    for (int i=tid; i<1152; i+=160) {
        int ocp = i/144, rem = i%144;
        s_w[i] = make_float2(w[(2*ocp)*144+rem], w[(2*ocp+1)*144+rem]);
    }
    if (tid<8) s_b[tid] = make_float2(bias[2*tid], bias[2*tid+1]);
    int row0g = tile*8 - 1;
    for (int i=tid; i<6720; i+=160) {
        int ic = i/420; int rem = i%420; int r = rem/42, c = rem%42;
        int ih = row0g + r, iw = c - 1;
        float v = 0.f;
        if (ih>=0 && ih<H2 && iw>=0 && iw<W2)
            v = g_tmp1[((b*C1+ic)*H2+ih)*W2+iw];
        s_in[i] = v;
    }
    __syncthreads();
    int owh = tid%20, oh_l = tid/20;
    float2 acc[2][8];
#pragma unroll
    for (int o=0;o<8;o++) { acc[0][o] = s_b[o]; acc[1][o] = s_b[o]; }
#pragma unroll 1
    for (int ic=0; ic<16; ic++) {
        const float* sp = s_in + ic*420;
#pragma unroll
        for (int k=0;k<9;k++) {
            int dy = k/3, dx = k%3;
            float2 wv[8];
#pragma unroll
            for (int o=0;o<8;o++) wv[o] = s_w[o*144 + ic*9 + k];
            float x0 = sp[(oh_l+dy)*42 + (2*owh  +dx)];
            float x1 = sp[(oh_l+dy)*42 + (2*owh+1+dx)];
#pragma unroll
            for (int o=0;o<8;o++) {
                acc[0][o] = ffma2(wv[o], x0, acc[0][o]);
                acc[1][o] = ffma2(wv[o], x1, acc[1][o]);
            }
        }
    }
    int oh = tile*8 + oh_l;
#pragma unroll
    for (int o=0;o<8;o++)
#pragma unroll
    for (int j=0;j<2;j++) {
        int ow = 2*owh + j;
        g_tmp2[((b*C2 + 2*o  )*H2 + oh)*W2 + ow] = fmaxf(acc[j][o].x, 0.f);
        g_tmp2[((b*C2 + 2*o+1)*H2 + oh)*W2 + ow] = fmaxf(acc[j][o].y, 0.f);
    }
}

// ---------- conv3 (16->32) + relu + maxpool(4,2) -> GRU layout ----------
__global__ __launch_bounds__(160) void k_conv3pool(const float* __restrict__ w,
                                                   const float* __restrict__ bias) {
    __shared__ float  s_in[16*10*42];
    __shared__ float2 s_w[16*144];
    __shared__ float2 s_b[16];
    int tid = threadIdx.x;
    int b = blockIdx.x/20, ohp = blockIdx.x%20;
    for (int i=tid; i<2304; i+=160) {
        int ocp = i/144, rem = i%144;
        s_w[i] = make_float2(w[(2*ocp)*144+rem], w[(2*ocp+1)*144+rem]);
    }
    if (tid<16) s_b[tid] = make_float2(bias[2*tid], bias[2*tid+1]);
    int row0g = ohp*8 - 1;
    for (int i=tid; i<6720; i+=160) {
        int ic = i/420; int rem = i%420; int r = rem/42, c = rem%42;
        int ih = row0g + r, iw = c - 1;
        float v = 0.f;
        if (ih>=0 && ih<H2 && iw>=0 && iw<W2)
            v = g_tmp2[((b*C2+ic)*H2+ih)*W2+iw];
        s_in[i] = v;
    }
    __syncthreads();
    int ow = tid%20; int rest = tid/20;
    int oh_l = rest%2; int ocg = rest/2;
    float2 acc[8][4];
#pragma unroll
    for (int p=0;p<8;p++)
#pragma unroll
    for (int j=0;j<4;j++) acc[p][j] = s_b[ocg*4+j];
#pragma unroll 1
    for (int ic=0; ic<16; ic++) {
        const float* sp = s_in + ic*420;
#pragma unroll
        for (int k=0;k<9;k++) {
            int dy = k/3, dx = k%3;
            float2 wv[4];
#pragma unroll
            for (int j=0;j<4;j++) wv[j] = s_w[(ocg*4+j)*144 + ic*9 + k];
#pragma unroll
            for (int pr=0;pr<4;pr++)
#pragma unroll
            for (int pc=0;pc<2;pc++) {
                float xv = sp[(4*oh_l+pr+dy)*42 + (2*ow+pc+dx)];
                int p = pr*2+pc;
#pragma unroll
                for (int j=0;j<4;j++) acc[p][j] = ffma2(wv[j], xv, acc[p][j]);
            }
        }
    }
    int t = ohp*2 + oh_l;
#pragma unroll
    for (int j=0;j<4;j++) {
        float2 m = acc[0][j];
#pragma unroll
        for (int p=1;p<8;p++) m = fmax2(m, acc[p][j]);
        int oc0 = 2*(ocg*4+j);
        g_x[(b*TT + t)*IG + ow*32 + oc0    ] = fmaxf(m.x, 0.f);
        g_x[(b*TT + t)*IG + ow*32 + oc0 + 1] = fmaxf(m.y, 0.f);
    }
}

// ---------------- gx GEMM: (2560 x 1536) = x @ W_ih^T + b_ih ----------------
__global__ __launch_bounds__(256) void k_gemm(const float* __restrict__ wf,
                                              const float* __restrict__ wb,
                                              const float* __restrict__ bf,
                                              const float* __restrict__ bb) {
    __shared__ float As[16*132];
    __shared__ float Bs[16*68];
    int tid = threadIdx.x;
    int bm = blockIdx.x % 20, bn = blockIdx.x / 20;
    int m0 = bm*128, n0 = bn*64;
    int d = (n0 >= 768) ? 1 : 0;
    const float* wsrc = d ? wb : wf;
    const float* bsrc = d ? bb : bf;
    int g0 = n0 - d*768;
    int tx = tid%16, ty = tid/16;
    float acc[8][4];
#pragma unroll
    for (int i=0;i<8;i++)
#pragma unroll
    for (int j=0;j<4;j++) acc[i][j] = 0.f;

    for (int kt=0; kt<40; kt++) {
        int k0 = kt*16;
#pragma unroll
        for (int l=0;l<2;l++) {
            int idx = tid + l*256;
            int row = idx>>2, k4 = idx&3;
            int m = m0 + row; int t = m>>6; int bb_ = m&63;
            float4 v = *(const float4*)(g_x + (size_t)(bb_*TT + t)*IG + k0 + k4*4);
            As[(k4*4+0)*132 + row] = v.x;
            As[(k4*4+1)*132 + row] = v.y;
            As[(k4*4+2)*132 + row] = v.z;
            As[(k4*4+3)*132 + row] = v.w;
        }
        {
            int n = tid>>2, k4 = tid&3;
            float4 v = *(const float4*)(wsrc + (size_t)(g0+n)*IG + k0 + k4*4);
            Bs[(k4*4+0)*68 + n] = v.x;
            Bs[(k4*4+1)*68 + n] = v.y;
            Bs[(k4*4+2)*68 + n] = v.z;
            Bs[(k4*4+3)*68 + n] = v.w;
        }
        __syncthreads();
#pragma unroll
        for (int k=0;k<16;k++) {
            float4 a0 = *(const float4*)(As + k*132 + ty*8);
            float4 a1 = *(const float4*)(As + k*132 + ty*8 + 4);
            float4 bv = *(const float4*)(Bs + k*68 + tx*4);
            float av[8] = {a0.x,a0.y,a0.z,a0.w,a1.x,a1.y,a1.z,a1.w};
            float bw[4] = {bv.x,bv.y,bv.z,bv.w};
#pragma unroll
            for (int i=0;i<8;i++)
#pragma unroll
            for (int j=0;j<4;j++) acc[i][j] += av[i]*bw[j];
        }
        __syncthreads();
    }
#pragma unroll
    for (int i=0;i<8;i++) {
        int m = m0 + ty*8 + i; int t = m>>6; int bb_ = m&63;
        float* op = g_gx + (size_t)((d*TT + t)*NB + bb_)*G3 + g0 + tx*4;
#pragma unroll
        for (int j=0;j<4;j++) op[j] = acc[i][j] + bsrc[g0 + tx*4 + j];
    }
}

// -------- persistent bidirectional GRU recurrence, grouped spin barrier --------
// 128 blocks: dir(2) x hidden-slice(8 x 32 units) x batch-group(8 x 8 batches)
__global__ __launch_bounds__(192) void k_gru(const float* __restrict__ whf,
                                             const float* __restrict__ whb,
                                             const float* __restrict__ bhf,
                                             const float* __restrict__ bhb,
                                             float* __restrict__ out) {
    extern __shared__ float sm[];
    float* w_s   = sm;                   // 96 x 260 (padded)
    float* h_s   = sm + 96*260;          // 8 x 260
    float* gh_s  = h_s + 8*260;          // 8 x 96
    float* bhh_s = gh_s + 8*96;          // 96
    int tid = threadIdx.x;
    int bx = blockIdx.x;
    int s     = bx & 7;
    int group = bx >> 3;
    int d     = group >> 3;
    int bgrp  = group & 7;
    const float* whh = d ? whb : whf;
    const float* bhh = d ? bhb : bhf;

    for (int i=tid; i<96*64; i+=192) {
        int r = i>>6, k4 = i&63;
        int c = r>>5, u = r&31;
        int grow = c*256 + s*32 + u;
        *(float4*)(w_s + r*260 + k4*4) =
            *(const float4*)(whh + (size_t)grow*256 + k4*4);
    }
    for (int i=tid; i<96; i+=192) {
        int c = i>>5, u = i&31;
        bhh_s[i] = bhh[c*256 + s*32 + u];
    }
    __syncthreads();

    int r  = tid % 96;
    int bh = tid / 96;
    const float4* wp = (const float4*)(w_s + r*260);
    int b0 = bgrp*8;

    for (int step=0; step<40; step++) {
        int p = step & 1;
        const float* hsrc = g_h[p] + (size_t)(d*NB + b0)*HID;
        for (int i=tid; i<8*64; i+=192) {
            int bi = i>>6, k4 = i&63;
            float4 v = *(const float4*)(hsrc + bi*HID + k4*4);
            *(float4*)(h_s + bi*260 + k4*4) = v;
        }
        __syncthreads();

        const float4* hA = (const float4*)(h_s + (bh*4+0)*260);
        const float4* hB = (const float4*)(h_s + (bh*4+1)*260);
        const float4* hC = (const float4*)(h_s + (bh*4+2)*260);
        const float4* hD = (const float4*)(h_s + (bh*4+3)*260);
        float a0=0.f, a1=0.f, a2=0.f, a3=0.f;
#pragma unroll 8
        for (int k=0;k<64;k++) {
            float4 wv = wp[k];
            float4 h0 = hA[k]; a0 += wv.x*h0.x + wv.y*h0.y + wv.z*h0.z + wv.w*h0.w;
            float4 h1 = hB[k]; a1 += wv.x*h1.x + wv.y*h1.y + wv.z*h1.z + wv.w*h1.w;
            float4 h2 = hC[k]; a2 += wv.x*h2.x + wv.y*h2.y + wv.z*h2.z + wv.w*h2.w;
            float4 h3 = hD[k]; a3 += wv.x*h3.x + wv.y*h3.y + wv.z*h3.z + wv.w*h3.w;
        }
        gh_s[(bh*4+0)*96 + r] = a0;
        gh_s[(bh*4+1)*96 + r] = a1;
        gh_s[(bh*4+2)*96 + r] = a2;
        gh_s[(bh*4+3)*96 + r] = a3;
        __syncthreads();

        int t = d ? (39 - step) : step;
        for (int i=tid; i<256; i+=192) {
            int bi = i>>5, u = i&31;
            float hr = gh_s[bi*96      + u] + bhh_s[u];
            float hz = gh_s[bi*96 + 32 + u] + bhh_s[32+u];
            float hn = gh_s[bi*96 + 64 + u] + bhh_s[64+u];
            const float* gx = g_gx + (size_t)((d*TT + t)*NB + b0 + bi)*G3 + s*32 + u;
            float xr = gx[0], xz = gx[256], xn = gx[512];
            float hold = h_s[bi*260 + s*32 + u];
            float rg = 1.f/(1.f + expf(-(xr+hr)));
            float zg = 1.f/(1.f + expf(-(xz+hz)));
            float ng = tanhf(xn + rg*hn);
            float hnew = (1.f - zg)*ng + zg*hold;
            g_h[p^1][(size_t)(d*NB + b0 + bi)*HID + s*32 + u] = hnew;
            out[((size_t)(b0+bi)*TT + t)*512 + d*256 + s*32 + u] = hnew;
            if (step == 39)
                out[(size_t)NB*TT*512 + (size_t)(d*NB + b0 + bi)*HID + s*32 + u] = hnew;
        }
        __threadfence();
        __syncthreads();
        if (tid == 0) {
            atomicAdd(&g_ctr[group], 1u);
            unsigned target = 8u*(unsigned)(step+1);
            while (atomicAdd(&g_ctr[group], 0u) < target) __nanosleep(64);
            __threadfence();
        }
        __syncthreads();
    }
}

// ---------------- launcher ----------------
extern "C" void kernel_launch(void* const* d_in, const int* in_sizes, int n_in,
                              void* d_out, int out_size) {
    const float* img  = (const float*)d_in[0];
    const float* hid  = (const float*)d_in[1];
    const float* c0w  = (const float*)d_in[2];
    const float* c0b  = (const float*)d_in[3];
    const float* c1w  = (const float*)d_in[4];
    const float* c1b  = (const float*)d_in[5];
    const float* c2w  = (const float*)d_in[6];
    const float* c2b  = (const float*)d_in[7];
    const float* c3w  = (const float*)d_in[8];
    const float* c3b  = (const float*)d_in[9];
    const float* wihf = (const float*)d_in[10];
    const float* whhf = (const float*)d_in[11];
    const float* bihf = (const float*)d_in[12];
    const float* bhhf = (const float*)d_in[13];
    const float* wihb = (const float*)d_in[14];
    const float* whhb = (const float*)d_in[15];
    const float* bihb = (const float*)d_in[16];
    const float* bhhb = (const float*)d_in[17];
    float* out = (float*)d_out;

    static int smem_set = 0;
    const int GRU_SMEM = (96*260 + 8*260 + 8*96 + 96) * 4;
    if (!smem_set) {
        cudaFuncSetAttribute(k_gru, cudaFuncAttributeMaxDynamicSharedMemorySize,
                             GRU_SMEM);
        smem_set = 1;
    }

    k_prep<<<128, 256>>>(hid);
    k_conv0<<<NB*HIN*WIN/256, 256>>>(img, c0w, c0b);
    k_conv1pool<<<NB*40, 160>>>(c1w, c1b);
    k_conv2<<<NB*20, 160>>>(c2w, c2b);
    k_conv3pool<<<NB*20, 160>>>(c3w, c3b);
    k_gemm<<<480, 256>>>(wihf, wihb, bihf, bihb);
    k_gru<<<128, 192, GRU_SMEM>>>(whhf, whhb, bhhf, bhhb, out);
}

// round 6
// speedup vs baseline: 1.0479x; 1.0479x over previous
#include <cuda_runtime.h>

#define NB   64
#define HIN  480
#define WIN  80
#define C0   8
#define C1   16
#define C2   16
#define C3   32
#define H2   160
#define W2   40
#define TT   40
#define W5   20
#define IG   640
#define HID  256
#define G3   768

// ---------------- device scratch ----------------
__device__ float g_tmp0[NB*C0*HIN*WIN];   // conv0 out (relu)
__device__ float g_tmp1[NB*C1*H2*W2];     // pool(relu(conv1))
__device__ float g_tmp2[NB*C2*H2*W2];     // relu(conv2)
__device__ float g_x[NB*TT*IG];           // GRU input (b,t,640)
__device__ float g_gx[2*TT*NB*G3];        // gate preacts, both dirs
__device__ float g_h[2][2*NB*HID];        // double-buffered hidden

// packed fp32x2 FMA (Blackwell)
__device__ __forceinline__ float2 ffma2(float2 w, float x, float2 c) {
    float2 r;
    asm("{\n\t"
        ".reg .b64 wa, xb, cc, dd;\n\t"
        "mov.b64 wa, {%2,%3};\n\t"
        "mov.b64 xb, {%4,%4};\n\t"
        "mov.b64 cc, {%5,%6};\n\t"
        "fma.rn.f32x2 dd, wa, xb, cc;\n\t"
        "mov.b64 {%0,%1}, dd;\n\t"
        "}" : "=f"(r.x), "=f"(r.y)
            : "f"(w.x), "f"(w.y), "f"(x), "f"(c.x), "f"(c.y));
    return r;
}
// packed fp32x2 FMA, both operands vectors (for GEMM: b-pair * a-scalar)
__device__ __forceinline__ float2 ffma2v(float2 b, float a, float2 c) {
    return ffma2(b, a, c);
}
__device__ __forceinline__ float2 fmax2(float2 a, float2 b) {
    return make_float2(fmaxf(a.x,b.x), fmaxf(a.y,b.y));
}

// ---------------- prep: copy h0 ----------------
__global__ void k_prep(const float* __restrict__ hidden) {
    int i = blockIdx.x*256 + threadIdx.x;
    if (i < 2*NB*HID) g_h[0][i] = hidden[i];
}

// ---------------- conv0: 1->8, 3x3 pad1, relu ----------------
__global__ __launch_bounds__(256) void k_conv0(const float* __restrict__ in,
                                               const float* __restrict__ w,
                                               const float* __restrict__ bias) {
    __shared__ float2 sw[36];
    __shared__ float2 sb[4];
    int tid = threadIdx.x;
    if (tid < 36) { int ocp = tid/9, k = tid%9;
        sw[tid] = make_float2(w[(2*ocp)*9+k], w[(2*ocp+1)*9+k]); }
    if (tid < 4) sb[tid] = make_float2(bias[2*tid], bias[2*tid+1]);
    __syncthreads();
    int gid = blockIdx.x*256 + tid;
    int x = gid % WIN; int y = (gid/WIN) % HIN; int b = gid/(WIN*HIN);
    const float* ip = in + (size_t)b*HIN*WIN;
    float v[9];
#pragma unroll
    for (int dy=0; dy<3; dy++)
#pragma unroll
    for (int dx=0; dx<3; dx++) {
        int yy = y+dy-1, xx = x+dx-1;
        v[dy*3+dx] = (yy>=0 && yy<HIN && xx>=0 && xx<WIN) ? ip[yy*WIN+xx] : 0.f;
    }
#pragma unroll
    for (int ocp=0; ocp<4; ocp++) {
        float2 acc = sb[ocp];
#pragma unroll
        for (int k=0;k<9;k++) acc = ffma2(sw[ocp*9+k], v[k], acc);
        g_tmp0[((b*C0 + 2*ocp  )*HIN + y)*WIN + x] = fmaxf(acc.x, 0.f);
        g_tmp0[((b*C0 + 2*ocp+1)*HIN + y)*WIN + x] = fmaxf(acc.y, 0.f);
    }
}

// ------- conv1 (8->16) + relu + maxpool(3x2 win, 3x2 stride), restructured -------
// block: 256 thr (240 compute), tile = 2 pool rows (6 conv rows), grid = 64*80
__global__ __launch_bounds__(256) void k_conv1pool(const float* __restrict__ w,
                                                   const float* __restrict__ bias) {
    __shared__ float  s_in[8*8*82];      // 5248: 8ic x 8 rows x 82 cols
    __shared__ float2 s_w[8*72];
    __shared__ float2 s_b[8];
    __shared__ float2 s_part[6*40*8];    // [convrow][poolcol][ocp]
    int tid = threadIdx.x;
    int b = blockIdx.x/80, tileP = blockIdx.x%80;
    for (int i=tid; i<576; i+=256) {
        int ocp = i/72, rem = i%72;
        s_w[i] = make_float2(w[(2*ocp)*72+rem], w[(2*ocp+1)*72+rem]);
    }
    if (tid<8) s_b[tid] = make_float2(bias[2*tid], bias[2*tid+1]);
    int r0g = tileP*6 - 1;
    for (int i=tid; i<5248; i+=256) {
        int ic = i/656; int rem = i%656; int r = rem/82, c = rem%82;
        int ih = r0g + r, iw = c - 1;
        float v = 0.f;
        if (ih>=0 && ih<HIN && iw>=0 && iw<WIN)
            v = g_tmp0[((b*C0+ic)*HIN+ih)*WIN+iw];
        s_in[i] = v;
    }
    __syncthreads();
    if (tid < 240) {
        int pc = tid % 40;              // pool col (conv cols 2pc, 2pc+1)
        int row = tid / 40;             // conv row in block 0..5
        float2 acc[2][8];
#pragma unroll
        for (int o=0;o<8;o++) { acc[0][o] = s_b[o]; acc[1][o] = s_b[o]; }
#pragma unroll 1
        for (int ic=0; ic<8; ic++) {
            const float* sp = s_in + ic*656;
#pragma unroll
            for (int k=0;k<9;k++) {
                int dy = k/3, dx = k%3;
                float2 wv[8];
#pragma unroll
                for (int o=0;o<8;o++) wv[o] = s_w[o*72 + ic*9 + k];
                float x0 = sp[(row+dy)*82 + (2*pc  +dx)];
                float x1 = sp[(row+dy)*82 + (2*pc+1+dx)];
#pragma unroll
                for (int o=0;o<8;o++) {
                    acc[0][o] = ffma2(wv[o], x0, acc[0][o]);
                    acc[1][o] = ffma2(wv[o], x1, acc[1][o]);
                }
            }
        }
#pragma unroll
        for (int o=0;o<8;o++)
            s_part[(row*40 + pc)*8 + o] = fmax2(acc[0][o], acc[1][o]);
    }
    __syncthreads();
    for (int i=tid; i<640; i+=256) {
        int o = i%8; int pc = (i/8)%40; int pr = i/320;  // pr 0..1
        float2 m = s_part[((3*pr  )*40 + pc)*8 + o];
        m = fmax2(m, s_part[((3*pr+1)*40 + pc)*8 + o]);
        m = fmax2(m, s_part[((3*pr+2)*40 + pc)*8 + o]);
        int oh = tileP*2 + pr;
        g_tmp1[((b*C1 + 2*o  )*H2 + oh)*W2 + pc] = fmaxf(m.x, 0.f);
        g_tmp1[((b*C1 + 2*o+1)*H2 + oh)*W2 + pc] = fmaxf(m.y, 0.f);
    }
}

// ---------------- conv2: 16->16, 3x3 pad1, relu (16-row tile, dyn smem) ----------
__global__ __launch_bounds__(320) void k_conv2(const float* __restrict__ w,
                                               const float* __restrict__ bias) {
    extern __shared__ float smx[];
    float*  s_in = smx;                         // 16 x 18 x 42 = 12096
    float2* s_w  = (float2*)(smx + 12096);      // 8*144
    float2* s_b  = (float2*)(smx + 12096 + 2304);
    int tid = threadIdx.x;
    int b = blockIdx.x/10, tile = blockIdx.x%10;
    for (int i=tid; i<1152; i+=320) {
        int ocp = i/144, rem = i%144;
        s_w[i] = make_float2(w[(2*ocp)*144+rem], w[(2*ocp+1)*144+rem]);
    }
    if (tid<8) s_b[tid] = make_float2(bias[2*tid], bias[2*tid+1]);
    int r0g = tile*16 - 1;
    for (int i=tid; i<12096; i+=320) {
        int ic = i/756; int rem = i%756; int r = rem/42, c = rem%42;
        int ih = r0g + r, iw = c - 1;
        float v = 0.f;
        if (ih>=0 && ih<H2 && iw>=0 && iw<W2)
            v = g_tmp1[((b*C1+ic)*H2+ih)*W2+iw];
        s_in[i] = v;
    }
    __syncthreads();
    int pc = tid % 20;                 // conv cols 2pc, 2pc+1
    int row = tid / 20;                // 0..15
    float2 acc[2][8];
#pragma unroll
    for (int o=0;o<8;o++) { acc[0][o] = s_b[o]; acc[1][o] = s_b[o]; }
#pragma unroll 1
    for (int ic=0; ic<16; ic++) {
        const float* sp = s_in + ic*756;
#pragma unroll
        for (int k=0;k<9;k++) {
            int dy = k/3, dx = k%3;
            float2 wv[8];
#pragma unroll
            for (int o=0;o<8;o++) wv[o] = s_w[o*144 + ic*9 + k];
            float x0 = sp[(row+dy)*42 + (2*pc  +dx)];
            float x1 = sp[(row+dy)*42 + (2*pc+1+dx)];
#pragma unroll
            for (int o=0;o<8;o++) {
                acc[0][o] = ffma2(wv[o], x0, acc[0][o]);
                acc[1][o] = ffma2(wv[o], x1, acc[1][o]);
            }
        }
    }
    int oh = tile*16 + row;
#pragma unroll
    for (int o=0;o<8;o++)
#pragma unroll
    for (int j=0;j<2;j++) {
        int ow = 2*pc + j;
        g_tmp2[((b*C2 + 2*o  )*H2 + oh)*W2 + ow] = fmaxf(acc[j][o].x, 0.f);
        g_tmp2[((b*C2 + 2*o+1)*H2 + oh)*W2 + ow] = fmaxf(acc[j][o].y, 0.f);
    }
}

// ---- conv3 (16->32) + relu + maxpool(4x2) -> GRU layout (restructured) ----
// block 320 thr: pc(20) x row(8) x ocg(2, 8 oc-pairs each), tile = 2 pool rows
__global__ __launch_bounds__(320) void k_conv3pool(const float* __restrict__ w,
                                                   const float* __restrict__ bias) {
    extern __shared__ float smx[];
    float*  s_in   = smx;                        // 16 x 10 x 42 = 6720
    float2* s_w    = (float2*)(smx + 6720);      // 16*144 = 2304 f2
    float2* s_b    = (float2*)(smx + 6720 + 4608);  // 16 f2
    float2* s_part = (float2*)(smx + 6720 + 4608 + 32); // 8*20*16 = 2560 f2
    int tid = threadIdx.x;
    int b = blockIdx.x/20, tileP = blockIdx.x%20;
    for (int i=tid; i<2304; i+=320) {
        int ocp = i/144, rem = i%144;
        s_w[i] = make_float2(w[(2*ocp)*144+rem], w[(2*ocp+1)*144+rem]);
    }
    if (tid<16) s_b[tid] = make_float2(bias[2*tid], bias[2*tid+1]);
    int r0g = tileP*8 - 1;
    for (int i=tid; i<6720; i+=320) {
        int ic = i/420; int rem = i%420; int r = rem/42, c = rem%42;
        int ih = r0g + r, iw = c - 1;
        float v = 0.f;
        if (ih>=0 && ih<H2 && iw>=0 && iw<W2)
            v = g_tmp2[((b*C2+ic)*H2+ih)*W2+iw];
        s_in[i] = v;
    }
    __syncthreads();
    {
        int pc  = tid % 20;            // pool col (conv cols 2pc, 2pc+1)
        int row = (tid/20) % 8;        // conv row in block 0..7
        int ocg = tid / 160;           // 0..1 -> oc-pairs ocg*8..+7
        float2 acc[2][8];
#pragma unroll
        for (int o=0;o<8;o++) { acc[0][o] = s_b[ocg*8+o]; acc[1][o] = s_b[ocg*8+o]; }
#pragma unroll 1
        for (int ic=0; ic<16; ic++) {
            const float* sp = s_in + ic*420;
#pragma unroll
            for (int k=0;k<9;k++) {
                int dy = k/3, dx = k%3;
                float2 wv[8];
#pragma unroll
                for (int o=0;o<8;o++) wv[o] = s_w[(ocg*8+o)*144 + ic*9 + k];
                float x0 = sp[(row+dy)*42 + (2*pc  +dx)];
                float x1 = sp[(row+dy)*42 + (2*pc+1+dx)];
#pragma unroll
                for (int o=0;o<8;o++) {
                    acc[0][o] = ffma2(wv[o], x0, acc[0][o]);
                    acc[1][o] = ffma2(wv[o], x1, acc[1][o]);
                }
            }
        }
#pragma unroll
        for (int o=0;o<8;o++)
            s_part[(row*20 + pc)*16 + ocg*8 + o] = fmax2(acc[0][o], acc[1][o]);
    }
    __syncthreads();
    for (int i=tid; i<640; i+=320) {
        int o = i%16; int pc = (i/16)%20; int pr = i/320;  // pr 0..1
        float2 m = s_part[((4*pr  )*20 + pc)*16 + o];
        m = fmax2(m, s_part[((4*pr+1)*20 + pc)*16 + o]);
        m = fmax2(m, s_part[((4*pr+2)*20 + pc)*16 + o]);
        m = fmax2(m, s_part[((4*pr+3)*20 + pc)*16 + o]);
        int t = tileP*2 + pr;
        g_x[(b*TT + t)*IG + pc*32 + 2*o    ] = fmaxf(m.x, 0.f);
        g_x[(b*TT + t)*IG + pc*32 + 2*o + 1] = fmaxf(m.y, 0.f);
    }
}

// -------- gx GEMM: (2560 x 1536) = x @ W_ih^T + b_ih, f32x2 packed --------
__global__ __launch_bounds__(256) void k_gemm(const float* __restrict__ wf,
                                              const float* __restrict__ wb,
                                              const float* __restrict__ bf,
                                              const float* __restrict__ bb) {
    __shared__ float As[16*132];
    __shared__ float Bs[16*68];
    int tid = threadIdx.x;
    int bm = blockIdx.x % 20, bn = blockIdx.x / 20;
    int m0 = bm*128, n0 = bn*64;
    int d = (n0 >= 768) ? 1 : 0;
    const float* wsrc = d ? wb : wf;
    const float* bsrc = d ? bb : bf;
    int g0 = n0 - d*768;
    int tx = tid%16, ty = tid/16;
    float2 acc[8][2];
#pragma unroll
    for (int i=0;i<8;i++)
#pragma unroll
    for (int j=0;j<2;j++) acc[i][j] = make_float2(0.f, 0.f);

    for (int kt=0; kt<40; kt++) {
        int k0 = kt*16;
#pragma unroll
        for (int l=0;l<2;l++) {
            int idx = tid + l*256;
            int row = idx>>2, k4 = idx&3;
            int m = m0 + row; int t = m>>6; int bb_ = m&63;
            float4 v = *(const float4*)(g_x + (size_t)(bb_*TT + t)*IG + k0 + k4*4);
            As[(k4*4+0)*132 + row] = v.x;
            As[(k4*4+1)*132 + row] = v.y;
            As[(k4*4+2)*132 + row] = v.z;
            As[(k4*4+3)*132 + row] = v.w;
        }
        {
            int n = tid>>2, k4 = tid&3;
            float4 v = *(const float4*)(wsrc + (size_t)(g0+n)*IG + k0 + k4*4);
            Bs[(k4*4+0)*68 + n] = v.x;
            Bs[(k4*4+1)*68 + n] = v.y;
            Bs[(k4*4+2)*68 + n] = v.z;
            Bs[(k4*4+3)*68 + n] = v.w;
        }
        __syncthreads();
#pragma unroll
        for (int k=0;k<16;k++) {
            float4 a0 = *(const float4*)(As + k*132 + ty*8);
            float4 a1 = *(const float4*)(As + k*132 + ty*8 + 4);
            float4 bv = *(const float4*)(Bs + k*68 + tx*4);
            float2 b01 = make_float2(bv.x, bv.y);
            float2 b23 = make_float2(bv.z, bv.w);
            float av[8] = {a0.x,a0.y,a0.z,a0.w,a1.x,a1.y,a1.z,a1.w};
#pragma unroll
            for (int i=0;i<8;i++) {
                acc[i][0] = ffma2v(b01, av[i], acc[i][0]);
                acc[i][1] = ffma2v(b23, av[i], acc[i][1]);
            }
        }
        __syncthreads();
    }
#pragma unroll
    for (int i=0;i<8;i++) {
        int m = m0 + ty*8 + i; int t = m>>6; int bb_ = m&63;
        float* op = g_gx + (size_t)((d*TT + t)*NB + bb_)*G3 + g0 + tx*4;
        op[0] = acc[i][0].x + bsrc[g0 + tx*4 + 0];
        op[1] = acc[i][0].y + bsrc[g0 + tx*4 + 1];
        op[2] = acc[i][1].x + bsrc[g0 + tx*4 + 2];
        op[3] = acc[i][1].y + bsrc[g0 + tx*4 + 3];
    }
}

// -------- persistent bidirectional GRU, cluster-of-8 barrier --------
// 128 blocks = 16 clusters; cluster = (dir, batch-group of 8), CTA = hidden slice
__global__ __launch_bounds__(192) __cluster_dims__(8,1,1)
void k_gru(const float* __restrict__ whf,
           const float* __restrict__ whb,
           const float* __restrict__ bhf,
           const float* __restrict__ bhb,
           float* __restrict__ out) {
    extern __shared__ float sm[];
    float* w_s   = sm;                   // 96 x 260 (padded)
    float* h_s   = sm + 96*260;          // 8 x 260
    float* gh_s  = h_s + 8*260;          // 8 x 96
    float* bhh_s = gh_s + 8*96;          // 96
    int tid = threadIdx.x;
    int bx = blockIdx.x;
    int s     = bx & 7;                  // cluster rank = hidden slice
    int group = bx >> 3;
    int d     = group >> 3;
    int bgrp  = group & 7;
    const float* whh = d ? whb : whf;
    const float* bhh = d ? bhb : bhf;

    for (int i=tid; i<96*64; i+=192) {
        int r = i>>6, k4 = i&63;
        int c = r>>5, u = r&31;
        int grow = c*256 + s*32 + u;
        *(float4*)(w_s + r*260 + k4*4) =
            *(const float4*)(whh + (size_t)grow*256 + k4*4);
    }
    for (int i=tid; i<96; i+=192) {
        int c = i>>5, u = i&31;
        bhh_s[i] = bhh[c*256 + s*32 + u];
    }
    __syncthreads();

    int r  = tid % 96;
    int bh = tid / 96;
    const float4* wp = (const float4*)(w_s + r*260);
    int b0 = bgrp*8;

    for (int step=0; step<40; step++) {
        int p = step & 1;
        int t = d ? (39 - step) : step;

        // prefetch gx for epilogue (hide global latency behind the dot phase)
        float pre[2][3];
#pragma unroll
        for (int j=0;j<2;j++) {
            int i = tid + 192*j;
            if (i < 256) {
                int bi = i>>5, u = i&31;
                const float* gx = g_gx + (size_t)((d*TT + t)*NB + b0 + bi)*G3 + s*32 + u;
                pre[j][0] = __ldcg(gx);
                pre[j][1] = __ldcg(gx + 256);
                pre[j][2] = __ldcg(gx + 512);
            }
        }

        const float* hsrc = g_h[p] + (size_t)(d*NB + b0)*HID;
        for (int i=tid; i<8*64; i+=192) {
            int bi = i>>6, k4 = i&63;
            float4 v = __ldcg((const float4*)(hsrc + bi*HID + k4*4));
            *(float4*)(h_s + bi*260 + k4*4) = v;
        }
        __syncthreads();

        const float4* hA = (const float4*)(h_s + (bh*4+0)*260);
        const float4* hB = (const float4*)(h_s + (bh*4+1)*260);
        const float4* hC = (const float4*)(h_s + (bh*4+2)*260);
        const float4* hD = (const float4*)(h_s + (bh*4+3)*260);
        float a0=0.f, a1=0.f, a2=0.f, a3=0.f;
#pragma unroll 8
        for (int k=0;k<64;k++) {
            float4 wv = wp[k];
            float4 h0 = hA[k]; a0 += wv.x*h0.x + wv.y*h0.y + wv.z*h0.z + wv.w*h0.w;
            float4 h1 = hB[k]; a1 += wv.x*h1.x + wv.y*h1.y + wv.z*h1.z + wv.w*h1.w;
            float4 h2 = hC[k]; a2 += wv.x*h2.x + wv.y*h2.y + wv.z*h2.z + wv.w*h2.w;
            float4 h3 = hD[k]; a3 += wv.x*h3.x + wv.y*h3.y + wv.z*h3.z + wv.w*h3.w;
        }
        gh_s[(bh*4+0)*96 + r] = a0;
        gh_s[(bh*4+1)*96 + r] = a1;
        gh_s[(bh*4+2)*96 + r] = a2;
        gh_s[(bh*4+3)*96 + r] = a3;
        __syncthreads();

#pragma unroll
        for (int j=0;j<2;j++) {
            int i = tid + 192*j;
            if (i < 256) {
                int bi = i>>5, u = i&31;
                float hr = gh_s[bi*96      + u] + bhh_s[u];
                float hz = gh_s[bi*96 + 32 + u] + bhh_s[32+u];
                float hn = gh_s[bi*96 + 64 + u] + bhh_s[64+u];
                float hold = h_s[bi*260 + s*32 + u];
                float rg = 1.f/(1.f + expf(-(pre[j][0]+hr)));
                float zg = 1.f/(1.f + expf(-(pre[j][1]+hz)));
                float ng = tanhf(pre[j][2] + rg*hn);
                float hnew = (1.f - zg)*ng + zg*hold;
                g_h[p^1][(size_t)(d*NB + b0 + bi)*HID + s*32 + u] = hnew;
                out[((size_t)(b0+bi)*TT + t)*512 + d*256 + s*32 + u] = hnew;
                if (step == 39)
                    out[(size_t)NB*TT*512 + (size_t)(d*NB + b0 + bi)*HID + s*32 + u] = hnew;
            }
        }
        __threadfence();
        asm volatile("barrier.cluster.arrive.aligned;" ::: "memory");
        asm volatile("barrier.cluster.wait.aligned;"  ::: "memory");
    }
}

// ---------------- launcher ----------------
extern "C" void kernel_launch(void* const* d_in, const int* in_sizes, int n_in,
                              void* d_out, int out_size) {
    const float* img  = (const float*)d_in[0];
    const float* hid  = (const float*)d_in[1];
    const float* c0w  = (const float*)d_in[2];
    const float* c0b  = (const float*)d_in[3];
    const float* c1w  = (const float*)d_in[4];
    const float* c1b  = (const float*)d_in[5];
    const float* c2w  = (const float*)d_in[6];
    const float* c2b  = (const float*)d_in[7];
    const float* c3w  = (const float*)d_in[8];
    const float* c3b  = (const float*)d_in[9];
    const float* wihf = (const float*)d_in[10];
    const float* whhf = (const float*)d_in[11];
    const float* bihf = (const float*)d_in[12];
    const float* bhhf = (const float*)d_in[13];
    const float* wihb = (const float*)d_in[14];
    const float* whhb = (const float*)d_in[15];
    const float* bihb = (const float*)d_in[16];
    const float* bhhb = (const float*)d_in[17];
    float* out = (float*)d_out;

    const int CONV2_SMEM = (12096 + 2304 + 16) * 4;           // 57664
    const int CONV3_SMEM = (6720 + 4608 + 32 + 5120) * 4;     // 65920
    const int GRU_SMEM   = (96*260 + 8*260 + 8*96 + 96) * 4;  // 111616
    cudaFuncSetAttribute(k_conv2, cudaFuncAttributeMaxDynamicSharedMemorySize, CONV2_SMEM);
    cudaFuncSetAttribute(k_conv3pool, cudaFuncAttributeMaxDynamicSharedMemorySize, CONV3_SMEM);
    cudaFuncSetAttribute(k_gru, cudaFuncAttributeMaxDynamicSharedMemorySize, GRU_SMEM);

    k_prep<<<128, 256>>>(hid);
    k_conv0<<<NB*HIN*WIN/256, 256>>>(img, c0w, c0b);
    k_conv1pool<<<NB*80, 256>>>(c1w, c1b);
    k_conv2<<<NB*10, 320, CONV2_SMEM>>>(c2w, c2b);
    k_conv3pool<<<NB*20, 320, CONV3_SMEM>>>(c3w, c3b);
    k_gemm<<<480, 256>>>(wihf, wihb, bihf, bihb);
    k_gru<<<128, 192, GRU_SMEM>>>(whhf, whhb, bhhf, bhhb, out);
}